// round 3
// baseline (speedup 1.0000x reference)
#include <cuda_runtime.h>
#include <cuda_bf16.h>
#include <cstdint>

#define B_   4
#define SM_  1024
#define SI_  4096
#define D_   256
#define H_   8
#define FF_  1024
#define MROWS (B_*SM_)   // 4096
#define IROWS (B_*SI_)   // 16384

typedef __nv_bfloat16  bf16;
typedef __nv_bfloat162 bf162;

// ---------------- scratch (static device globals) --------------------------
__device__ bf16  g_ib  [IROWS*D_];
__device__ bf16  g_sb  [MROWS*D_];
__device__ bf16  g_Wkb [D_*D_];
__device__ bf16  g_Wvb [D_*D_];
__device__ bf16  g_Wqb [H_*D_*D_];
__device__ bf16  g_Wob [H_*D_*D_];
__device__ bf16  g_Winb[D_*FF_];
__device__ bf16  g_Wgnlb[FF_*FF_];
__device__ bf16  g_Wglb [FF_*FF_];
__device__ bf16  g_Wgob [FF_*D_];
__device__ bf16  g_ikb [IROWS*D_];
__device__ bf16  g_ivb [IROWS*D_];
__device__ bf16  g_mkb [MROWS*D_];
__device__ float g_mvf [MROWS*D_];
__device__ bf16  g_qb  [H_*MROWS*D_];
__device__ bf16  g_ccb [MROWS*H_*D_];
__device__ float g_y   [MROWS*D_];
__device__ float g_x   [MROWS*D_];
__device__ bf16  g_xb  [MROWS*D_];
__device__ bf16  g_hb  [MROWS*FF_];
__device__ float g_t1  [MROWS*FF_];
__device__ float g_t2  [MROWS*FF_];
__device__ bf16  g_gb  [MROWS*FF_];
__device__ float g_y2  [MROWS*D_];

// ---------------- PTX helpers ----------------------------------------------
__device__ __forceinline__ uint32_t sptr(const void* p){
    return (uint32_t)__cvta_generic_to_shared(p);
}
__device__ __forceinline__ void ldsm4(uint32_t a[4], uint32_t addr){
    asm volatile("ldmatrix.sync.aligned.m8n8.x4.shared.b16 {%0,%1,%2,%3},[%4];"
        : "=r"(a[0]),"=r"(a[1]),"=r"(a[2]),"=r"(a[3]) : "r"(addr));
}
__device__ __forceinline__ void ldsm4t(uint32_t a[4], uint32_t addr){
    asm volatile("ldmatrix.sync.aligned.m8n8.x4.trans.shared.b16 {%0,%1,%2,%3},[%4];"
        : "=r"(a[0]),"=r"(a[1]),"=r"(a[2]),"=r"(a[3]) : "r"(addr));
}
__device__ __forceinline__ void mma16816(float c[4], const uint32_t a[4], const uint32_t b[2]){
    asm volatile("mma.sync.aligned.m16n8k16.row.col.f32.bf16.bf16.f32 "
        "{%0,%1,%2,%3},{%4,%5,%6,%7},{%8,%9},{%0,%1,%2,%3};"
        : "+f"(c[0]),"+f"(c[1]),"+f"(c[2]),"+f"(c[3])
        : "r"(a[0]),"r"(a[1]),"r"(a[2]),"r"(a[3]),"r"(b[0]),"r"(b[1]));
}
__device__ __forceinline__ void cp16(uint32_t dst, const void* src){
    asm volatile("cp.async.cg.shared.global [%0],[%1],16;" :: "r"(dst),"l"(src));
}
__device__ __forceinline__ void cpcommit(){ asm volatile("cp.async.commit_group;"); }
__device__ __forceinline__ void cpwait0(){ asm volatile("cp.async.wait_group 0;"); }
__device__ __forceinline__ void cpwait1(){ asm volatile("cp.async.wait_group 1;"); }

// ---------------- convert fp32 -> bf16 -------------------------------------
__global__ void cvt_bf16(const float* __restrict__ s, bf16* __restrict__ d, int n){
    int i = (blockIdx.x*blockDim.x + threadIdx.x)*4;
    if (i < n){
        float4 v = *(const float4*)(s+i);
        *(bf162*)(d+i)   = __floats2bfloat162_rn(v.x, v.y);
        *(bf162*)(d+i+2) = __floats2bfloat162_rn(v.z, v.w);
    }
}

// ---------------- bf16 GEMM: C = A[M,K] @ B[K,N] + bias --------------------
// OUTMODE: 0 bf16, 1 bf16+relu, 2 f32, 3 f32+residual R
template<int OUTMODE>
__global__ void __launch_bounds__(256) gemm_bf(
    const bf16* __restrict__ A, const bf16* __restrict__ Bw,
    const float* __restrict__ bias, const float* __restrict__ R,
    void* __restrict__ Cout, int M, int N, int K,
    long sB, long sBias, long sC)
{
    __shared__ __align__(16) bf16 smA[2][128*32];
    __shared__ __align__(16) bf16 smB[2][32*128];

    const int z = blockIdx.z;
    Bw   += (size_t)z*sB;
    bias += (size_t)z*sBias;

    const int m0 = blockIdx.y*128, n0 = blockIdx.x*128;
    const int t = threadIdx.x;
    const int w = t>>5, lane = t&31;
    const int wm = w>>1, wn = w&1;

    auto loadA = [&](int st, int k0){
        #pragma unroll
        for (int i=0;i<2;++i){
            int idx = t + i*256;             // 0..511
            int r = idx>>2, c = idx&3;
            int csw = c ^ ((r>>1)&3);
            cp16(sptr(&smA[st][(r*4+csw)*8]), A + (size_t)(m0+r)*K + k0 + c*8);
        }
    };
    auto loadB = [&](int st, int k0){
        #pragma unroll
        for (int i=0;i<2;++i){
            int idx = t + i*256;
            int r = idx>>4, c = idx&15;
            int csw = c ^ (r&7);
            cp16(sptr(&smB[st][(r*16+csw)*8]), Bw + (size_t)(k0+r)*N + n0 + c*8);
        }
    };

    float acc[2][8][4] = {};

    loadA(0,0); loadB(0,0); cpcommit();
    const int KT = K>>5;
    for (int kt=0; kt<KT; ++kt){
        int st = kt&1;
        if (kt+1<KT){ loadA(st^1,(kt+1)*32); loadB(st^1,(kt+1)*32); cpcommit(); cpwait1(); }
        else cpwait0();
        __syncthreads();

        #pragma unroll
        for (int ks=0; ks<2; ++ks){
            uint32_t af[2][4];
            #pragma unroll
            for (int mt=0; mt<2; ++mt){
                int r = wm*32 + mt*16 + (lane&7) + ((lane>>3)&1)*8;
                int c = ks*2 + (lane>>4);
                int csw = c ^ ((r>>1)&3);
                ldsm4(af[mt], sptr(&smA[st][(r*4+csw)*8]));
            }
            #pragma unroll
            for (int np=0; np<4; ++np){
                uint32_t bfr[4];
                int kr = ks*16 + (lane&7) + ((lane>>3)&1)*8;
                int c  = (wn*64 + np*16)/8 + (lane>>4);
                int csw = c ^ (kr&7);
                ldsm4t(bfr, sptr(&smB[st][(kr*16+csw)*8]));
                mma16816(acc[0][np*2+0], af[0], &bfr[0]);
                mma16816(acc[0][np*2+1], af[0], &bfr[2]);
                mma16816(acc[1][np*2+0], af[1], &bfr[0]);
                mma16816(acc[1][np*2+1], af[1], &bfr[2]);
            }
        }
        __syncthreads();
    }

    const int rbase = m0 + wm*32 + (lane>>2);
    const int cbase = n0 + wn*64 + (lane&3)*2;
    #pragma unroll
    for (int mt=0; mt<2; ++mt){
        #pragma unroll
        for (int nt=0; nt<8; ++nt){
            int row = rbase + mt*16;
            int col = cbase + nt*8;
            float b0 = bias[col], b1 = bias[col+1];
            float v0 = acc[mt][nt][0]+b0, v1 = acc[mt][nt][1]+b1;
            float v2 = acc[mt][nt][2]+b0, v3 = acc[mt][nt][3]+b1;
            if (OUTMODE==1){
                v0=fmaxf(v0,0.f); v1=fmaxf(v1,0.f); v2=fmaxf(v2,0.f); v3=fmaxf(v3,0.f);
            }
            if (OUTMODE==3){
                float2 r0 = *(const float2*)(R + (size_t)row*N + col);
                float2 r1 = *(const float2*)(R + (size_t)(row+8)*N + col);
                v0+=r0.x; v1+=r0.y; v2+=r1.x; v3+=r1.y;
            }
            if (OUTMODE<=1){
                bf16* C = (bf16*)Cout + (size_t)z*sC;
                *(bf162*)(C + (size_t)row*N + col)     = __floats2bfloat162_rn(v0,v1);
                *(bf162*)(C + (size_t)(row+8)*N + col) = __floats2bfloat162_rn(v2,v3);
            } else {
                float* C = (float*)Cout + (size_t)z*sC;
                *(float2*)(C + (size_t)row*N + col)     = make_float2(v0,v1);
                *(float2*)(C + (size_t)(row+8)*N + col) = make_float2(v2,v3);
            }
        }
    }
}

// ---------------- flash attention (bf16 HMMA) -------------------------------
// Q tile 64 rows, K/V tiles 64 keys, D=256. Self-token folded into init state.
#define FL_K(st) (32768 + (st)*65536)
#define FL_V(st) (65536 + (st)*65536)
#define FL_P 163840
#define FL_STAT 173056
#define FLASH_SMEM (174848 + 256)

__global__ void __launch_bounds__(256,1) flash_bf()
{
    extern __shared__ __align__(16) char sm[];
    bf16*  Qs = (bf16*)(sm);
    bf16*  Ps = (bf16*)(sm + FL_P);           // [64][72]
    float* rmax   = (float*)(sm + FL_STAT);
    float* rsum   = rmax + 64;
    float* ralpha = rsum + 64;
    float* pmax   = ralpha + 64;              // [64][2]
    float* psum   = pmax + 128;               // [64][2]

    const int t = threadIdx.x, w = t>>5, lane = t&31;
    const int h = blockIdx.y, b = blockIdx.z;
    const int m0 = blockIdx.x*64;

    auto qkvoff = [](int r, int c){ return (r*32 + (c ^ (r&7)))*8; };

    // Q load (+ tile0, tile1 prefetch)
    const bf16* qg = g_qb + ((size_t)h*MROWS + (size_t)b*SM_ + m0)*D_;
    #pragma unroll
    for (int i=0;i<8;++i){
        int idx = t + i*256;
        int r = idx>>5, c = idx&31;
        cp16(sptr(Qs + qkvoff(r,c)), qg + (size_t)r*D_ + c*8);
    }
    auto loadKV = [&](int tile, int st){
        const bf16* kg = g_ikb + ((size_t)b*SI_ + tile*64)*D_;
        const bf16* vg = g_ivb + ((size_t)b*SI_ + tile*64)*D_;
        bf16* Ks = (bf16*)(sm + FL_K(st));
        bf16* Vs = (bf16*)(sm + FL_V(st));
        #pragma unroll
        for (int i=0;i<8;++i){
            int idx = t + i*256;
            int r = idx>>5, c = idx&31;
            int off = qkvoff(r,c);
            cp16(sptr(Ks + off), kg + (size_t)r*D_ + c*8);
            cp16(sptr(Vs + off), vg + (size_t)r*D_ + c*8);
        }
    };
    loadKV(0,0); cpcommit();
    loadKV(1,1); cpcommit();
    cpwait1(); __syncthreads();   // Q + tile0 ready

    // self-score init: rmax = (q . mk)/16, rsum = 1
    {
        int row = t>>2, quad = t&3;
        const bf16* mk = g_mkb + ((size_t)b*SM_ + m0 + row)*D_;
        float s = 0.f;
        #pragma unroll
        for (int cc=0; cc<8; ++cc){
            int c = quad*8 + cc;
            const bf162* q2 = (const bf162*)(Qs + qkvoff(row,c));
            const bf162* k2 = (const bf162*)(mk + c*8);
            #pragma unroll
            for (int j=0;j<4;++j){
                float2 qv = __bfloat1622float2(q2[j]);
                float2 kv = __bfloat1622float2(k2[j]);
                s += qv.x*kv.x + qv.y*kv.y;
            }
        }
        s += __shfl_xor_sync(~0u, s, 1);
        s += __shfl_xor_sync(~0u, s, 2);
        if (quad==0){ rmax[row] = s*0.0625f; rsum[row] = 1.f; }
    }

    // O init = mv (fp32)
    const int mh = w>>2, nq = w&3;
    float o[2][8][4];
    {
        const float* mv = g_mvf + ((size_t)b*SM_ + m0)*D_;
        #pragma unroll
        for (int mt=0;mt<2;++mt){
            int r0 = mh*32 + mt*16 + (lane>>2);
            #pragma unroll
            for (int nt=0;nt<8;++nt){
                int col = nq*64 + nt*8 + (lane&3)*2;
                float2 v0 = *(const float2*)(mv + (size_t)r0*D_ + col);
                float2 v1 = *(const float2*)(mv + (size_t)(r0+8)*D_ + col);
                o[mt][nt][0]=v0.x; o[mt][nt][1]=v0.y; o[mt][nt][2]=v1.x; o[mt][nt][3]=v1.y;
            }
        }
    }
    __syncthreads();

    const int sw_m = w>>1, sw_n = w&1;
    const int NT = SI_/64;

    for (int tile=0; tile<NT; ++tile){
        int st = tile&1;
        bf16* Ks = (bf16*)(sm + FL_K(st));
        bf16* Vs = (bf16*)(sm + FL_V(st));

        // S = Q @ K^T (warp: 16 rows x 32 keys)
        float sa[4][4] = {};
        #pragma unroll
        for (int ks=0; ks<16; ++ks){
            uint32_t af[4];
            {
                int r = sw_m*16 + (lane&7) + ((lane>>3)&1)*8;
                int c = ks*2 + (lane>>4);
                ldsm4(af, sptr(Qs + qkvoff(r,c)));
            }
            #pragma unroll
            for (int np=0; np<2; ++np){
                uint32_t bfr[4];
                int r = sw_n*32 + np*16 + (lane&7) + ((lane>>4)&1)*8;
                int c = ks*2 + ((lane>>3)&1);
                ldsm4(bfr, sptr(Ks + qkvoff(r,c)));
                mma16816(sa[np*2+0], af, &bfr[0]);
                mma16816(sa[np*2+1], af, &bfr[2]);
            }
        }
        #pragma unroll
        for (int i=0;i<4;++i){
            sa[i][0]*=0.0625f; sa[i][1]*=0.0625f; sa[i][2]*=0.0625f; sa[i][3]*=0.0625f;
        }

        // row max (partial across this warp's 32 cols)
        float mx0 = -1e30f, mx1 = -1e30f;
        #pragma unroll
        for (int i=0;i<4;++i){
            mx0 = fmaxf(mx0, fmaxf(sa[i][0], sa[i][1]));
            mx1 = fmaxf(mx1, fmaxf(sa[i][2], sa[i][3]));
        }
        mx0 = fmaxf(mx0, __shfl_xor_sync(~0u, mx0, 1));
        mx0 = fmaxf(mx0, __shfl_xor_sync(~0u, mx0, 2));
        mx1 = fmaxf(mx1, __shfl_xor_sync(~0u, mx1, 1));
        mx1 = fmaxf(mx1, __shfl_xor_sync(~0u, mx1, 2));
        if ((lane&3)==0){
            int r = sw_m*16 + (lane>>2);
            pmax[r*2 + sw_n] = mx0;
            pmax[(r+8)*2 + sw_n] = mx1;
        }
        __syncthreads();
        if (t < 64){
            float mnew = fmaxf(rmax[t], fmaxf(pmax[t*2], pmax[t*2+1]));
            ralpha[t] = __expf(rmax[t]-mnew);
            rmax[t] = mnew;
        }
        __syncthreads();

        // exp + P store + partial sums
        {
            int r0 = sw_m*16 + (lane>>2);
            float m0r = rmax[r0], m1r = rmax[r0+8];
            float s0 = 0.f, s1 = 0.f;
            #pragma unroll
            for (int i=0;i<4;++i){
                sa[i][0] = __expf(sa[i][0]-m0r); sa[i][1] = __expf(sa[i][1]-m0r);
                sa[i][2] = __expf(sa[i][2]-m1r); sa[i][3] = __expf(sa[i][3]-m1r);
                s0 += sa[i][0]+sa[i][1]; s1 += sa[i][2]+sa[i][3];
                int col = sw_n*32 + i*8 + (lane&3)*2;
                *(bf162*)(Ps + r0*72 + col)     = __floats2bfloat162_rn(sa[i][0], sa[i][1]);
                *(bf162*)(Ps + (r0+8)*72 + col) = __floats2bfloat162_rn(sa[i][2], sa[i][3]);
            }
            s0 += __shfl_xor_sync(~0u,s0,1); s0 += __shfl_xor_sync(~0u,s0,2);
            s1 += __shfl_xor_sync(~0u,s1,1); s1 += __shfl_xor_sync(~0u,s1,2);
            if ((lane&3)==0){ psum[r0*2+sw_n]=s0; psum[(r0+8)*2+sw_n]=s1; }
        }
        __syncthreads();
        if (t<64) rsum[t] = rsum[t]*ralpha[t] + psum[t*2] + psum[t*2+1];

        // O = O*alpha + P @ V  (warp: 32 rows x 64 d-cols)
        #pragma unroll
        for (int mt=0;mt<2;++mt){
            int r0 = mh*32 + mt*16 + (lane>>2);
            float a0 = ralpha[r0], a1 = ralpha[r0+8];
            #pragma unroll
            for (int nt=0;nt<8;++nt){
                o[mt][nt][0]*=a0; o[mt][nt][1]*=a0; o[mt][nt][2]*=a1; o[mt][nt][3]*=a1;
            }
        }
        #pragma unroll
        for (int ks=0; ks<4; ++ks){
            uint32_t af[2][4];
            #pragma unroll
            for (int mt=0;mt<2;++mt){
                int r = mh*32 + mt*16 + (lane&7) + ((lane>>3)&1)*8;
                int c = ks*2 + (lane>>4);
                ldsm4(af[mt], sptr(Ps + r*72 + c*8));
            }
            #pragma unroll
            for (int np=0;np<4;++np){
                uint32_t bfr[4];
                int kr = ks*16 + (lane&7) + ((lane>>3)&1)*8;
                int c  = (nq*64 + np*16)/8 + (lane>>4);
                ldsm4t(bfr, sptr(Vs + qkvoff(kr,c)));
                mma16816(o[0][np*2+0], af[0], &bfr[0]);
                mma16816(o[0][np*2+1], af[0], &bfr[2]);
                mma16816(o[1][np*2+0], af[1], &bfr[0]);
                mma16816(o[1][np*2+1], af[1], &bfr[2]);
            }
        }
        __syncthreads();
        if (tile+2 < NT){ loadKV(tile+2, st); cpcommit(); cpwait1(); }
        else cpwait0();
        __syncthreads();
    }

    // final normalize + write concat (bf16)
    #pragma unroll
    for (int mt=0;mt<2;++mt){
        int r0 = mh*32 + mt*16 + (lane>>2);
        float i0 = 1.f/rsum[r0], i1 = 1.f/rsum[r0+8];
        bf16* c0 = g_ccb + ((size_t)(b*SM_ + m0 + r0)*(H_*D_)) + h*D_;
        bf16* c1 = g_ccb + ((size_t)(b*SM_ + m0 + r0 + 8)*(H_*D_)) + h*D_;
        #pragma unroll
        for (int nt=0;nt<8;++nt){
            int col = nq*64 + nt*8 + (lane&3)*2;
            *(bf162*)(c0+col) = __floats2bfloat162_rn(o[mt][nt][0]*i0, o[mt][nt][1]*i0);
            *(bf162*)(c1+col) = __floats2bfloat162_rn(o[mt][nt][2]*i1, o[mt][nt][3]*i1);
        }
    }
}

// ---------------- LayerNorm (last dim 256), optional bf16 copy --------------
__global__ void ln_kernel(const float* __restrict__ Y, const float* __restrict__ g,
                          const float* __restrict__ bb, float* __restrict__ X,
                          bf16* __restrict__ Xb)
{
    const int row = blockIdx.x;
    const int t = threadIdx.x;
    const float v = Y[(size_t)row*D_ + t];
    __shared__ float red[8];
    __shared__ float stat;

    float s = v;
    #pragma unroll
    for (int o = 16; o; o >>= 1) s += __shfl_xor_sync(0xffffffffu, s, o);
    if ((t & 31) == 0) red[t >> 5] = s;
    __syncthreads();
    if (t == 0) {
        float tot = 0.f;
        #pragma unroll
        for (int i = 0; i < 8; ++i) tot += red[i];
        stat = tot * (1.f / D_);
    }
    __syncthreads();
    const float mean = stat;
    const float d = v - mean;

    s = d * d;
    #pragma unroll
    for (int o = 16; o; o >>= 1) s += __shfl_xor_sync(0xffffffffu, s, o);
    __syncthreads();
    if ((t & 31) == 0) red[t >> 5] = s;
    __syncthreads();
    if (t == 0) {
        float tot = 0.f;
        #pragma unroll
        for (int i = 0; i < 8; ++i) tot += red[i];
        stat = tot * (1.f / D_);
    }
    __syncthreads();
    float out = d * rsqrtf(stat + 1e-6f) * g[t] + bb[t];
    X[(size_t)row*D_ + t] = out;
    if (Xb) Xb[(size_t)row*D_ + t] = __float2bfloat16(out);
}

// ---------------- gate multiply: g = bf16(relu(t1)*t2) ----------------------
__global__ void gate_mult(const float* __restrict__ t1, const float* __restrict__ t2,
                          bf16* __restrict__ gout, int n)
{
    int i = (blockIdx.x*blockDim.x + threadIdx.x)*2;
    if (i < n){
        float2 a = *(const float2*)(t1+i);
        float2 b = *(const float2*)(t2+i);
        *(bf162*)(gout+i) = __floats2bfloat162_rn(fmaxf(a.x,0.f)*b.x, fmaxf(a.y,0.f)*b.y);
    }
}

// ---------------- launch ----------------------------------------------------
extern "C" void kernel_launch(void* const* d_in, const int* in_sizes, int n_in,
                              void* d_out, int out_size)
{
    (void)in_sizes; (void)n_in; (void)out_size;
    const float* state = (const float*)d_in[0];
    const float* input = (const float*)d_in[1];
    const float* Wk    = (const float*)d_in[2];
    const float* bk    = (const float*)d_in[3];
    const float* Wv    = (const float*)d_in[4];
    const float* bv    = (const float*)d_in[5];
    const float* Wq    = (const float*)d_in[6];
    const float* bq    = (const float*)d_in[7];
    const float* Wo    = (const float*)d_in[8];
    const float* bo    = (const float*)d_in[9];
    const float* ln1g  = (const float*)d_in[10];
    const float* ln1b  = (const float*)d_in[11];
    const float* Win   = (const float*)d_in[12];
    const float* bin   = (const float*)d_in[13];
    const float* Wgnl  = (const float*)d_in[14];
    const float* bgnl  = (const float*)d_in[15];
    const float* Wgl   = (const float*)d_in[16];
    const float* bgl   = (const float*)d_in[17];
    const float* Wgo   = (const float*)d_in[18];
    const float* bgo   = (const float*)d_in[19];
    const float* ln2g  = (const float*)d_in[20];
    const float* ln2b  = (const float*)d_in[21];
    float* out = (float*)d_out;

    bf16 *ib,*sb,*Wkb,*Wvb,*Wqb,*Wob,*Winb,*Wgnlb,*Wglb,*Wgob;
    bf16 *ikb,*ivb,*mkb,*qb,*ccb,*xb,*hb,*gb;
    float *mvf,*y,*x,*t1,*t2,*y2;
    cudaGetSymbolAddress((void**)&ib,  g_ib);
    cudaGetSymbolAddress((void**)&sb,  g_sb);
    cudaGetSymbolAddress((void**)&Wkb, g_Wkb);
    cudaGetSymbolAddress((void**)&Wvb, g_Wvb);
    cudaGetSymbolAddress((void**)&Wqb, g_Wqb);
    cudaGetSymbolAddress((void**)&Wob, g_Wob);
    cudaGetSymbolAddress((void**)&Winb,g_Winb);
    cudaGetSymbolAddress((void**)&Wgnlb,g_Wgnlb);
    cudaGetSymbolAddress((void**)&Wglb, g_Wglb);
    cudaGetSymbolAddress((void**)&Wgob, g_Wgob);
    cudaGetSymbolAddress((void**)&ikb, g_ikb);
    cudaGetSymbolAddress((void**)&ivb, g_ivb);
    cudaGetSymbolAddress((void**)&mkb, g_mkb);
    cudaGetSymbolAddress((void**)&mvf, g_mvf);
    cudaGetSymbolAddress((void**)&qb,  g_qb);
    cudaGetSymbolAddress((void**)&ccb, g_ccb);
    cudaGetSymbolAddress((void**)&y,   g_y);
    cudaGetSymbolAddress((void**)&x,   g_x);
    cudaGetSymbolAddress((void**)&xb,  g_xb);
    cudaGetSymbolAddress((void**)&hb,  g_hb);
    cudaGetSymbolAddress((void**)&t1,  g_t1);
    cudaGetSymbolAddress((void**)&t2,  g_t2);
    cudaGetSymbolAddress((void**)&gb,  g_gb);
    cudaGetSymbolAddress((void**)&y2,  g_y2);

    cudaFuncSetAttribute(flash_bf, cudaFuncAttributeMaxDynamicSharedMemorySize, FLASH_SMEM);

    dim3 blk(256);
    auto cvt = [&](const float* s, bf16* d, int n){
        cvt_bf16<<<(n/4 + 255)/256, 256>>>(s, d, n);
    };
    // converts
    cvt(input, ib, IROWS*D_);
    cvt(state, sb, MROWS*D_);
    cvt(Wk,  Wkb,  D_*D_);
    cvt(Wv,  Wvb,  D_*D_);
    cvt(Wq,  Wqb,  H_*D_*D_);
    cvt(Wo,  Wob,  H_*D_*D_);
    cvt(Win, Winb, D_*FF_);
    cvt(Wgnl,Wgnlb,FF_*FF_);
    cvt(Wgl, Wglb, FF_*FF_);
    cvt(Wgo, Wgob, FF_*D_);

    // projections
    gemm_bf<0><<<dim3(D_/128, IROWS/128), blk>>>(ib, Wkb, bk, nullptr, ikb, IROWS, D_, D_, 0,0,0);
    gemm_bf<0><<<dim3(D_/128, IROWS/128), blk>>>(ib, Wvb, bv, nullptr, ivb, IROWS, D_, D_, 0,0,0);
    gemm_bf<0><<<dim3(D_/128, MROWS/128), blk>>>(sb, Wkb, bk, nullptr, mkb, MROWS, D_, D_, 0,0,0);
    gemm_bf<2><<<dim3(D_/128, MROWS/128), blk>>>(sb, Wvb, bv, nullptr, mvf, MROWS, D_, D_, 0,0,0);
    gemm_bf<0><<<dim3(D_/128, MROWS/128, H_), blk>>>(sb, Wqb, bq, nullptr, qb,
                                                     MROWS, D_, D_, (long)D_*D_, D_, (long)MROWS*D_);
    // flash attention
    flash_bf<<<dim3(SM_/64, H_, B_), blk, FLASH_SMEM>>>();
    // output proj + residual, LN1
    gemm_bf<3><<<dim3(D_/128, MROWS/128), blk>>>(ccb, Wob, bo, state, y, MROWS, D_, H_*D_, 0,0,0);
    ln_kernel<<<MROWS, D_>>>(y, ln1g, ln1b, x, xb);
    // FFN
    gemm_bf<1><<<dim3(FF_/128, MROWS/128), blk>>>(xb, Winb, bin, nullptr, hb, MROWS, FF_, D_, 0,0,0);
    gemm_bf<2><<<dim3(FF_/128, MROWS/128), blk>>>(hb, Wgnlb, bgnl, nullptr, t1, MROWS, FF_, FF_, 0,0,0);
    gemm_bf<2><<<dim3(FF_/128, MROWS/128), blk>>>(hb, Wglb,  bgl,  nullptr, t2, MROWS, FF_, FF_, 0,0,0);
    gate_mult<<<(MROWS*FF_/2 + 255)/256, 256>>>(t1, t2, gb, MROWS*FF_);
    gemm_bf<3><<<dim3(D_/128, MROWS/128), blk>>>(gb, Wgob, bgo, x, y2, MROWS, D_, FF_, 0,0,0);
    ln_kernel<<<MROWS, D_>>>(y2, ln2g, ln2b, out, nullptr);
}

// round 6
// speedup vs baseline: 1.0682x; 1.0682x over previous
#include <cuda_runtime.h>
#include <cuda_bf16.h>
#include <cstdint>

#define B_   4
#define SM_  1024
#define SI_  4096
#define D_   256
#define H_   8
#define FF_  1024
#define MROWS (B_*SM_)
#define IROWS (B_*SI_)

typedef __nv_bfloat16  bf16;
typedef __nv_bfloat162 bf162;

// ---------------- scratch -------------------------------------------------
__device__ bf16  g_ib  [IROWS*D_];
__device__ bf16  g_sb  [MROWS*D_];
__device__ bf16  g_Wkb [D_*D_];
__device__ bf16  g_Wvb [D_*D_];
__device__ bf16  g_Wqb [H_*D_*D_];
__device__ bf16  g_Wob [H_*D_*D_];
__device__ bf16  g_Winb[D_*FF_];
__device__ bf16  g_Wgnlb[FF_*FF_];
__device__ bf16  g_Wglb [FF_*FF_];
__device__ bf16  g_Wgob [FF_*D_];
__device__ bf16  g_ikb [IROWS*D_];
__device__ bf16  g_ivb [IROWS*D_];
__device__ bf16  g_mkb [MROWS*D_];
__device__ float g_mvf [MROWS*D_];
__device__ bf16  g_qb  [H_*MROWS*D_];
__device__ bf16  g_ccb [MROWS*H_*D_];
__device__ float g_y   [MROWS*D_];
__device__ float g_x   [MROWS*D_];
__device__ bf16  g_xb  [MROWS*D_];
__device__ bf16  g_hb  [MROWS*FF_];
__device__ bf16  g_gb  [MROWS*FF_];
__device__ float g_y2  [MROWS*D_];

// ---------------- helpers --------------------------------------------------
__device__ __forceinline__ uint32_t sptr(const void* p){
    return (uint32_t)__cvta_generic_to_shared(p);
}
__device__ __forceinline__ void ldsm4(uint32_t a[4], uint32_t addr){
    asm volatile("ldmatrix.sync.aligned.m8n8.x4.shared.b16 {%0,%1,%2,%3},[%4];"
        : "=r"(a[0]),"=r"(a[1]),"=r"(a[2]),"=r"(a[3]) : "r"(addr));
}
__device__ __forceinline__ void ldsm4t(uint32_t a[4], uint32_t addr){
    asm volatile("ldmatrix.sync.aligned.m8n8.x4.trans.shared.b16 {%0,%1,%2,%3},[%4];"
        : "=r"(a[0]),"=r"(a[1]),"=r"(a[2]),"=r"(a[3]) : "r"(addr));
}
__device__ __forceinline__ void mma16816(float c[4], const uint32_t a[4], const uint32_t b[2]){
    asm volatile("mma.sync.aligned.m16n8k16.row.col.f32.bf16.bf16.f32 "
        "{%0,%1,%2,%3},{%4,%5,%6,%7},{%8,%9},{%0,%1,%2,%3};"
        : "+f"(c[0]),"+f"(c[1]),"+f"(c[2]),"+f"(c[3])
        : "r"(a[0]),"r"(a[1]),"r"(a[2]),"r"(a[3]),"r"(b[0]),"r"(b[1]));
}
__device__ __forceinline__ void cp16(uint32_t dst, const void* src){
    asm volatile("cp.async.cg.shared.global [%0],[%1],16;" :: "r"(dst),"l"(src));
}
__device__ __forceinline__ void cpcommit(){ asm volatile("cp.async.commit_group;"); }
__device__ __forceinline__ void cpwait0(){ asm volatile("cp.async.wait_group 0;"); }
__device__ __forceinline__ void cpwait1(){ asm volatile("cp.async.wait_group 1;"); }

// ---------------- convert fp32 -> bf16 -------------------------------------
__global__ void cvt_bf16(const float* __restrict__ s, bf16* __restrict__ d, int n){
    int i = (blockIdx.x*blockDim.x + threadIdx.x)*4;
    if (i < n){
        float4 v = *(const float4*)(s+i);
        *(bf162*)(d+i)   = __floats2bfloat162_rn(v.x, v.y);
        *(bf162*)(d+i+2) = __floats2bfloat162_rn(v.z, v.w);
    }
}

// ---------------- bf16 GEMM (HMMA): C = A[M,K] @ B[K,N] + bias -------------
// OUTMODE: 0 bf16, 1 bf16+relu, 2 f32, 3 f32+residual R
template<int OUTMODE>
__global__ void __launch_bounds__(256) gemm_bf(
    const bf16* __restrict__ A, const bf16* __restrict__ Bw,
    const float* __restrict__ bias, const float* __restrict__ R,
    void* __restrict__ Cout, int M, int N, int K,
    long sB, long sBias, long sC)
{
    __shared__ __align__(16) bf16 smA[2][128*32];
    __shared__ __align__(16) bf16 smB[2][32*128];

    const int z = blockIdx.z;
    Bw   += (size_t)z*sB;
    bias += (size_t)z*sBias;

    const int m0 = blockIdx.y*128, n0 = blockIdx.x*128;
    const int t = threadIdx.x;
    const int w = t>>5, lane = t&31;
    const int wm = w>>1, wn = w&1;

    auto loadA = [&](int st, int k0){
        #pragma unroll
        for (int i=0;i<2;++i){
            int idx = t + i*256;
            int r = idx>>2, c = idx&3;
            int csw = c ^ ((r>>1)&3);
            cp16(sptr(&smA[st][(r*4+csw)*8]), A + (size_t)(m0+r)*K + k0 + c*8);
        }
    };
    auto loadB = [&](int st, int k0){
        #pragma unroll
        for (int i=0;i<2;++i){
            int idx = t + i*256;
            int r = idx>>4, c = idx&15;
            int csw = c ^ (r&7);
            cp16(sptr(&smB[st][(r*16+csw)*8]), Bw + (size_t)(k0+r)*N + n0 + c*8);
        }
    };

    float acc[2][8][4] = {};

    loadA(0,0); loadB(0,0); cpcommit();
    const int KT = K>>5;
    for (int kt=0; kt<KT; ++kt){
        int st = kt&1;
        if (kt+1<KT){ loadA(st^1,(kt+1)*32); loadB(st^1,(kt+1)*32); cpcommit(); cpwait1(); }
        else cpwait0();
        __syncthreads();

        #pragma unroll
        for (int ks=0; ks<2; ++ks){
            uint32_t af[2][4];
            #pragma unroll
            for (int mt=0; mt<2; ++mt){
                int r = wm*32 + mt*16 + (lane&7) + ((lane>>3)&1)*8;
                int c = ks*2 + (lane>>4);
                int csw = c ^ ((r>>1)&3);
                ldsm4(af[mt], sptr(&smA[st][(r*4+csw)*8]));
            }
            #pragma unroll
            for (int np=0; np<4; ++np){
                uint32_t bfr[4];
                int kr = ks*16 + (lane&7) + ((lane>>3)&1)*8;
                int c  = (wn*64 + np*16)/8 + (lane>>4);
                int csw = c ^ (kr&7);
                ldsm4t(bfr, sptr(&smB[st][(kr*16+csw)*8]));
                mma16816(acc[0][np*2+0], af[0], &bfr[0]);
                mma16816(acc[0][np*2+1], af[0], &bfr[2]);
                mma16816(acc[1][np*2+0], af[1], &bfr[0]);
                mma16816(acc[1][np*2+1], af[1], &bfr[2]);
            }
        }
        __syncthreads();
    }

    const int rbase = m0 + wm*32 + (lane>>2);
    const int cbase = n0 + wn*64 + (lane&3)*2;
    #pragma unroll
    for (int mt=0; mt<2; ++mt){
        #pragma unroll
        for (int nt=0; nt<8; ++nt){
            int row = rbase + mt*16;
            int col = cbase + nt*8;
            float b0 = bias[col], b1 = bias[col+1];
            float v0 = acc[mt][nt][0]+b0, v1 = acc[mt][nt][1]+b1;
            float v2 = acc[mt][nt][2]+b0, v3 = acc[mt][nt][3]+b1;
            if (OUTMODE==1){
                v0=fmaxf(v0,0.f); v1=fmaxf(v1,0.f); v2=fmaxf(v2,0.f); v3=fmaxf(v3,0.f);
            }
            if (OUTMODE==3){
                float2 r0 = *(const float2*)(R + (size_t)row*N + col);
                float2 r1 = *(const float2*)(R + (size_t)(row+8)*N + col);
                v0+=r0.x; v1+=r0.y; v2+=r1.x; v3+=r1.y;
            }
            if (OUTMODE<=1){
                bf16* C = (bf16*)Cout + (size_t)z*sC;
                *(bf162*)(C + (size_t)row*N + col)     = __floats2bfloat162_rn(v0,v1);
                *(bf162*)(C + (size_t)(row+8)*N + col) = __floats2bfloat162_rn(v2,v3);
            } else {
                float* C = (float*)Cout + (size_t)z*sC;
                *(float2*)(C + (size_t)row*N + col)     = make_float2(v0,v1);
                *(float2*)(C + (size_t)(row+8)*N + col) = make_float2(v2,v3);
            }
        }
    }
}

// ---------------- fused FFN gate: C = relu(A@B1+b1) * (A@B2+b2) ------------
// block tile 128x64, bf16 out
__global__ void __launch_bounds__(256) dualgate(
    const bf16* __restrict__ A,
    const bf16* __restrict__ B1, const float* __restrict__ b1,
    const bf16* __restrict__ B2, const float* __restrict__ b2,
    bf16* __restrict__ C, int M, int N, int K)
{
    __shared__ __align__(16) bf16 smA [2][128*32];
    __shared__ __align__(16) bf16 smB1[2][32*64];
    __shared__ __align__(16) bf16 smB2[2][32*64];

    const int m0 = blockIdx.y*128, n0 = blockIdx.x*64;
    const int t = threadIdx.x;
    const int w = t>>5, lane = t&31;
    const int wm = w>>1, wn = w&1;

    auto loadA = [&](int st, int k0){
        #pragma unroll
        for (int i=0;i<2;++i){
            int idx = t + i*256;
            int r = idx>>2, c = idx&3;
            int csw = c ^ ((r>>1)&3);
            cp16(sptr(&smA[st][(r*4+csw)*8]), A + (size_t)(m0+r)*K + k0 + c*8);
        }
    };
    auto loadB = [&](int st, int k0){
        int r = t>>3, c = t&7;
        int csw = c ^ (r&7);
        cp16(sptr(&smB1[st][(r*8+csw)*8]), B1 + (size_t)(k0+r)*N + n0 + c*8);
        cp16(sptr(&smB2[st][(r*8+csw)*8]), B2 + (size_t)(k0+r)*N + n0 + c*8);
    };

    float acc1[2][4][4] = {};
    float acc2[2][4][4] = {};

    loadA(0,0); loadB(0,0); cpcommit();
    const int KT = K>>5;
    for (int kt=0; kt<KT; ++kt){
        int st = kt&1;
        if (kt+1<KT){ loadA(st^1,(kt+1)*32); loadB(st^1,(kt+1)*32); cpcommit(); cpwait1(); }
        else cpwait0();
        __syncthreads();

        #pragma unroll
        for (int ks=0; ks<2; ++ks){
            uint32_t af[2][4];
            #pragma unroll
            for (int mt=0; mt<2; ++mt){
                int r = wm*32 + mt*16 + (lane&7) + ((lane>>3)&1)*8;
                int c = ks*2 + (lane>>4);
                int csw = c ^ ((r>>1)&3);
                ldsm4(af[mt], sptr(&smA[st][(r*4+csw)*8]));
            }
            #pragma unroll
            for (int np=0; np<2; ++np){
                int kr = ks*16 + (lane&7) + ((lane>>3)&1)*8;
                int c  = (wn*32 + np*16)/8 + (lane>>4);
                int csw = c ^ (kr&7);
                uint32_t f1[4], f2[4];
                ldsm4t(f1, sptr(&smB1[st][(kr*8+csw)*8]));
                ldsm4t(f2, sptr(&smB2[st][(kr*8+csw)*8]));
                mma16816(acc1[0][np*2+0], af[0], &f1[0]);
                mma16816(acc1[0][np*2+1], af[0], &f1[2]);
                mma16816(acc1[1][np*2+0], af[1], &f1[0]);
                mma16816(acc1[1][np*2+1], af[1], &f1[2]);
                mma16816(acc2[0][np*2+0], af[0], &f2[0]);
                mma16816(acc2[0][np*2+1], af[0], &f2[2]);
                mma16816(acc2[1][np*2+0], af[1], &f2[0]);
                mma16816(acc2[1][np*2+1], af[1], &f2[2]);
            }
        }
        __syncthreads();
    }

    const int rbase = m0 + wm*32 + (lane>>2);
    const int cbase = n0 + wn*32 + (lane&3)*2;
    #pragma unroll
    for (int mt=0; mt<2; ++mt){
        #pragma unroll
        for (int nt=0; nt<4; ++nt){
            int row = rbase + mt*16;
            int col = cbase + nt*8;
            float c10 = b1[col], c11 = b1[col+1];
            float c20 = b2[col], c21 = b2[col+1];
            float v0 = fmaxf(acc1[mt][nt][0]+c10, 0.f)*(acc2[mt][nt][0]+c20);
            float v1 = fmaxf(acc1[mt][nt][1]+c11, 0.f)*(acc2[mt][nt][1]+c21);
            float v2 = fmaxf(acc1[mt][nt][2]+c10, 0.f)*(acc2[mt][nt][2]+c20);
            float v3 = fmaxf(acc1[mt][nt][3]+c11, 0.f)*(acc2[mt][nt][3]+c21);
            *(bf162*)(C + (size_t)row*N + col)     = __floats2bfloat162_rn(v0,v1);
            *(bf162*)(C + (size_t)(row+8)*N + col) = __floats2bfloat162_rn(v2,v3);
        }
    }
}

// ---------------- flash attention v2: no-max softmax, 2 syncs/tile ---------
// smem: Q 32KB | K 2x32KB | V 3x32KB | P 64x72 bf16 | stats
#define FQ_OFF     0
#define FK_OFF(s)  (32768 + (s)*32768)
#define FV_OFF(s)  (98304 + (s)*32768)
#define FP_OFF     196608
#define FST_OFF    205824
#define FLASH_SMEM 206848
#define NT_        (SI_/64)

__global__ void __launch_bounds__(256,1) flash_bf2()
{
    extern __shared__ __align__(16) char sm[];
    bf16*  Qs     = (bf16*)(sm + FQ_OFF);
    bf16*  Ps     = (bf16*)(sm + FP_OFF);
    float* es_s   = (float*)(sm + FST_OFF);          // [64]
    float* rsum_s = (float*)(sm + FST_OFF + 256);    // [64]
    float* psum_s = (float*)(sm + FST_OFF + 512);    // [64][2]

    const int t = threadIdx.x, w = t>>5, lane = t&31;
    const int h = blockIdx.y, b = blockIdx.z;
    const int m0 = blockIdx.x*64;

    auto qkvoff = [](int r, int c){ return (r*32 + (c ^ (r&7)))*8; };

    // Q load + tile0 (group0), tile1 (group1)
    const bf16* qg = g_qb + ((size_t)h*MROWS + (size_t)b*SM_ + m0)*D_;
    #pragma unroll
    for (int i=0;i<8;++i){
        int idx = t + i*256;
        int r = idx>>5, c = idx&31;
        cp16(sptr(Qs + qkvoff(r,c)), qg + (size_t)r*D_ + c*8);
    }
    auto loadK = [&](int tile, int slot){
        const bf16* kg = g_ikb + ((size_t)b*SI_ + tile*64)*D_;
        bf16* Ks = (bf16*)(sm + FK_OFF(slot));
        #pragma unroll
        for (int i=0;i<8;++i){
            int idx = t + i*256;
            int r = idx>>5, c = idx&31;
            cp16(sptr(Ks + qkvoff(r,c)), kg + (size_t)r*D_ + c*8);
        }
    };
    auto loadV = [&](int tile, int slot){
        const bf16* vg = g_ivb + ((size_t)b*SI_ + tile*64)*D_;
        bf16* Vs = (bf16*)(sm + FV_OFF(slot));
        #pragma unroll
        for (int i=0;i<8;++i){
            int idx = t + i*256;
            int r = idx>>5, c = idx&31;
            cp16(sptr(Vs + qkvoff(r,c)), vg + (size_t)r*D_ + c*8);
        }
    };
    loadK(0,0); loadV(0,0); cpcommit();
    loadK(1,1); loadV(1,1); cpcommit();

    // self-score (from global, overlaps cp.async): es = exp(q . mk / 16)
    {
        int row = t>>2, quad = t&3;
        const bf162* q2 = (const bf162*)(qg + (size_t)row*D_ + quad*64);
        const bf162* k2 = (const bf162*)(g_mkb + ((size_t)b*SM_ + m0 + row)*D_ + quad*64);
        float s = 0.f;
        #pragma unroll
        for (int j=0;j<32;++j){
            float2 qv = __bfloat1622float2(q2[j]);
            float2 kv = __bfloat1622float2(k2[j]);
            s += qv.x*kv.x + qv.y*kv.y;
        }
        s += __shfl_xor_sync(~0u, s, 1);
        s += __shfl_xor_sync(~0u, s, 2);
        if (quad==0) es_s[row] = __expf(s*0.0625f);
    }
    __syncthreads();   // es visible

    // O init = es * mv
    const int mh = w>>2, nq = w&3;
    float o[2][8][4];
    {
        const float* mv = g_mvf + ((size_t)b*SM_ + m0)*D_;
        #pragma unroll
        for (int mt=0;mt<2;++mt){
            int r0 = mh*32 + mt*16 + (lane>>2);
            float e0 = es_s[r0], e1 = es_s[r0+8];
            #pragma unroll
            for (int nt=0;nt<8;++nt){
                int col = nq*64 + nt*8 + (lane&3)*2;
                float2 v0 = *(const float2*)(mv + (size_t)r0*D_ + col);
                float2 v1 = *(const float2*)(mv + (size_t)(r0+8)*D_ + col);
                o[mt][nt][0]=e0*v0.x; o[mt][nt][1]=e0*v0.y;
                o[mt][nt][2]=e1*v1.x; o[mt][nt][3]=e1*v1.y;
            }
        }
    }
    cpwait1(); __syncthreads();   // Q + tile0 ready

    const int sw_m = w>>1, sw_n = w&1;
    float ps0 = 0.f, ps1 = 0.f;   // running row-sum partials (score-phase rows)

    for (int i=0; i<NT_; ++i){
        bf16* Ks = (bf16*)(sm + FK_OFF(i&1));
        bf16* Vs = (bf16*)(sm + FV_OFF(i%3));

        // S = Q @ K^T (warp: 16 rows x 32 keys)
        float sa[4][4] = {};
        #pragma unroll
        for (int ks=0; ks<16; ++ks){
            uint32_t af[4];
            {
                int r = sw_m*16 + (lane&7) + ((lane>>3)&1)*8;
                int c = ks*2 + (lane>>4);
                ldsm4(af, sptr(Qs + qkvoff(r,c)));
            }
            #pragma unroll
            for (int np=0; np<2; ++np){
                uint32_t bfr[4];
                int r = sw_n*32 + np*16 + (lane&7) + ((lane>>4)&1)*8;
                int c = ks*2 + ((lane>>3)&1);
                ldsm4(bfr, sptr(Ks + qkvoff(r,c)));
                mma16816(sa[np*2+0], af, &bfr[0]);
                mma16816(sa[np*2+1], af, &bfr[2]);
            }
        }

        // exp (no max) + P store + accumulate row-sum partials
        {
            int r0 = sw_m*16 + (lane>>2);
            #pragma unroll
            for (int i4=0;i4<4;++i4){
                float p0 = __expf(sa[i4][0]*0.0625f);
                float p1 = __expf(sa[i4][1]*0.0625f);
                float p2 = __expf(sa[i4][2]*0.0625f);
                float p3 = __expf(sa[i4][3]*0.0625f);
                ps0 += p0 + p1;
                ps1 += p2 + p3;
                int col = sw_n*32 + i4*8 + (lane&3)*2;
                *(bf162*)(Ps + r0*72 + col)     = __floats2bfloat162_rn(p0,p1);
                *(bf162*)(Ps + (r0+8)*72 + col) = __floats2bfloat162_rn(p2,p3);
            }
        }
        __syncthreads();   // (a) P visible; S(i) + PV(i-1) complete everywhere

        // prefetch tile i+2: K into slot (i&1) [freed by S(i)], V into (i+2)%3 [freed by PV(i-1)]
        if (i+2 < NT_){ loadK(i+2, i&1); loadV(i+2, (i+2)%3); }
        cpcommit();

        // O += P @ V (warp: 32 rows x 64 d-cols)
        #pragma unroll
        for (int ks=0; ks<4; ++ks){
            uint32_t af[2][4];
            #pragma unroll
            for (int mt=0;mt<2;++mt){
                int r = mh*32 + mt*16 + (lane&7) + ((lane>>3)&1)*8;
                int c = ks*2 + (lane>>4);
                ldsm4(af[mt], sptr(Ps + r*72 + c*8));
            }
            #pragma unroll
            for (int np=0;np<4;++np){
                uint32_t bfr[4];
                int kr = ks*16 + (lane&7) + ((lane>>3)&1)*8;
                int c  = (nq*64 + np*16)/8 + (lane>>4);
                ldsm4t(bfr, sptr(Vs + qkvoff(kr,c)));
                mma16816(o[0][np*2+0], af[0], &bfr[0]);
                mma16816(o[0][np*2+1], af[0], &bfr[2]);
                mma16816(o[1][np*2+0], af[1], &bfr[0]);
                mma16816(o[1][np*2+1], af[1], &bfr[2]);
            }
        }
        cpwait1();
        __syncthreads();   // (b) tile i+1 visible; P free for overwrite
    }

    // reduce row sums: quad shfl, then combine with self term
    ps0 += __shfl_xor_sync(~0u, ps0, 1);
    ps0 += __shfl_xor_sync(~0u, ps0, 2);
    ps1 += __shfl_xor_sync(~0u, ps1, 1);
    ps1 += __shfl_xor_sync(~0u, ps1, 2);
    if ((lane&3)==0){
        int r0 = sw_m*16 + (lane>>2);
        psum_s[r0*2 + sw_n]     = ps0;
        psum_s[(r0+8)*2 + sw_n] = ps1;
    }
    __syncthreads();
    if (t < 64) rsum_s[t] = es_s[t] + psum_s[t*2] + psum_s[t*2+1];
    __syncthreads();

    // normalize + write concat (bf16)
    #pragma unroll
    for (int mt=0;mt<2;++mt){
        int r0 = mh*32 + mt*16 + (lane>>2);
        float i0 = 1.f/rsum_s[r0], i1 = 1.f/rsum_s[r0+8];
        bf16* c0 = g_ccb + ((size_t)(b*SM_ + m0 + r0)*(H_*D_)) + h*D_;
        bf16* c1 = g_ccb + ((size_t)(b*SM_ + m0 + r0 + 8)*(H_*D_)) + h*D_;
        #pragma unroll
        for (int nt=0;nt<8;++nt){
            int col = nq*64 + nt*8 + (lane&3)*2;
            *(bf162*)(c0+col) = __floats2bfloat162_rn(o[mt][nt][0]*i0, o[mt][nt][1]*i0);
            *(bf162*)(c1+col) = __floats2bfloat162_rn(o[mt][nt][2]*i1, o[mt][nt][3]*i1);
        }
    }
}

// ---------------- LayerNorm ------------------------------------------------
__global__ void ln_kernel(const float* __restrict__ Y, const float* __restrict__ g,
                          const float* __restrict__ bb, float* __restrict__ X,
                          bf16* __restrict__ Xb)
{
    const int row = blockIdx.x;
    const int t = threadIdx.x;
    const float v = Y[(size_t)row*D_ + t];
    __shared__ float red[8];
    __shared__ float stat;

    float s = v;
    #pragma unroll
    for (int o = 16; o; o >>= 1) s += __shfl_xor_sync(0xffffffffu, s, o);
    if ((t & 31) == 0) red[t >> 5] = s;
    __syncthreads();
    if (t == 0) {
        float tot = 0.f;
        #pragma unroll
        for (int i = 0; i < 8; ++i) tot += red[i];
        stat = tot * (1.f / D_);
    }
    __syncthreads();
    const float mean = stat;
    const float d = v - mean;

    s = d * d;
    #pragma unroll
    for (int o = 16; o; o >>= 1) s += __shfl_xor_sync(0xffffffffu, s, o);
    __syncthreads();
    if ((t & 31) == 0) red[t >> 5] = s;
    __syncthreads();
    if (t == 0) {
        float tot = 0.f;
        #pragma unroll
        for (int i = 0; i < 8; ++i) tot += red[i];
        stat = tot * (1.f / D_);
    }
    __syncthreads();
    float out = d * rsqrtf(stat + 1e-6f) * g[t] + bb[t];
    X[(size_t)row*D_ + t] = out;
    if (Xb) Xb[(size_t)row*D_ + t] = __float2bfloat16(out);
}

// ---------------- launch ----------------------------------------------------
extern "C" void kernel_launch(void* const* d_in, const int* in_sizes, int n_in,
                              void* d_out, int out_size)
{
    (void)in_sizes; (void)n_in; (void)out_size;
    const float* state = (const float*)d_in[0];
    const float* input = (const float*)d_in[1];
    const float* Wk    = (const float*)d_in[2];
    const float* bk    = (const float*)d_in[3];
    const float* Wv    = (const float*)d_in[4];
    const float* bv    = (const float*)d_in[5];
    const float* Wq    = (const float*)d_in[6];
    const float* bq    = (const float*)d_in[7];
    const float* Wo    = (const float*)d_in[8];
    const float* bo    = (const float*)d_in[9];
    const float* ln1g  = (const float*)d_in[10];
    const float* ln1b  = (const float*)d_in[11];
    const float* Win   = (const float*)d_in[12];
    const float* bin   = (const float*)d_in[13];
    const float* Wgnl  = (const float*)d_in[14];
    const float* bgnl  = (const float*)d_in[15];
    const float* Wgl   = (const float*)d_in[16];
    const float* bgl   = (const float*)d_in[17];
    const float* Wgo   = (const float*)d_in[18];
    const float* bgo   = (const float*)d_in[19];
    const float* ln2g  = (const float*)d_in[20];
    const float* ln2b  = (const float*)d_in[21];
    float* out = (float*)d_out;

    bf16 *ib,*sb,*Wkb,*Wvb,*Wqb,*Wob,*Winb,*Wgnlb,*Wglb,*Wgob;
    bf16 *ikb,*ivb,*mkb,*qb,*ccb,*xb,*hb,*gb;
    float *mvf,*y,*x,*y2;
    cudaGetSymbolAddress((void**)&ib,  g_ib);
    cudaGetSymbolAddress((void**)&sb,  g_sb);
    cudaGetSymbolAddress((void**)&Wkb, g_Wkb);
    cudaGetSymbolAddress((void**)&Wvb, g_Wvb);
    cudaGetSymbolAddress((void**)&Wqb, g_Wqb);
    cudaGetSymbolAddress((void**)&Wob, g_Wob);
    cudaGetSymbolAddress((void**)&Winb,g_Winb);
    cudaGetSymbolAddress((void**)&Wgnlb,g_Wgnlb);
    cudaGetSymbolAddress((void**)&Wglb, g_Wglb);
    cudaGetSymbolAddress((void**)&Wgob, g_Wgob);
    cudaGetSymbolAddress((void**)&ikb, g_ikb);
    cudaGetSymbolAddress((void**)&ivb, g_ivb);
    cudaGetSymbolAddress((void**)&mkb, g_mkb);
    cudaGetSymbolAddress((void**)&mvf, g_mvf);
    cudaGetSymbolAddress((void**)&qb,  g_qb);
    cudaGetSymbolAddress((void**)&ccb, g_ccb);
    cudaGetSymbolAddress((void**)&y,   g_y);
    cudaGetSymbolAddress((void**)&x,   g_x);
    cudaGetSymbolAddress((void**)&xb,  g_xb);
    cudaGetSymbolAddress((void**)&hb,  g_hb);
    cudaGetSymbolAddress((void**)&gb,  g_gb);
    cudaGetSymbolAddress((void**)&y2,  g_y2);

    cudaFuncSetAttribute(flash_bf2, cudaFuncAttributeMaxDynamicSharedMemorySize, FLASH_SMEM);

    dim3 blk(256);
    auto cvt = [&](const float* s, bf16* d, int n){
        cvt_bf16<<<(n/4 + 255)/256, 256>>>(s, d, n);
    };
    cvt(input, ib, IROWS*D_);
    cvt(state, sb, MROWS*D_);
    cvt(Wk,  Wkb,  D_*D_);
    cvt(Wv,  Wvb,  D_*D_);
    cvt(Wq,  Wqb,  H_*D_*D_);
    cvt(Wo,  Wob,  H_*D_*D_);
    cvt(Win, Winb, D_*FF_);
    cvt(Wgnl,Wgnlb,FF_*FF_);
    cvt(Wgl, Wglb, FF_*FF_);
    cvt(Wgo, Wgob, FF_*D_);

    gemm_bf<0><<<dim3(D_/128, IROWS/128), blk>>>(ib, Wkb, bk, nullptr, ikb, IROWS, D_, D_, 0,0,0);
    gemm_bf<0><<<dim3(D_/128, IROWS/128), blk>>>(ib, Wvb, bv, nullptr, ivb, IROWS, D_, D_, 0,0,0);
    gemm_bf<0><<<dim3(D_/128, MROWS/128), blk>>>(sb, Wkb, bk, nullptr, mkb, MROWS, D_, D_, 0,0,0);
    gemm_bf<2><<<dim3(D_/128, MROWS/128), blk>>>(sb, Wvb, bv, nullptr, mvf, MROWS, D_, D_, 0,0,0);
    gemm_bf<0><<<dim3(D_/128, MROWS/128, H_), blk>>>(sb, Wqb, bq, nullptr, qb,
                                                     MROWS, D_, D_, (long)D_*D_, D_, (long)MROWS*D_);
    flash_bf2<<<dim3(SM_/64, H_, B_), blk, FLASH_SMEM>>>();
    gemm_bf<3><<<dim3(D_/128, MROWS/128), blk>>>(ccb, Wob, bo, state, y, MROWS, D_, H_*D_, 0,0,0);
    ln_kernel<<<MROWS, D_>>>(y, ln1g, ln1b, x, xb);
    gemm_bf<1><<<dim3(FF_/128, MROWS/128), blk>>>(xb, Winb, bin, nullptr, hb, MROWS, FF_, D_, 0,0,0);
    dualgate<<<dim3(FF_/64, MROWS/128), blk>>>(hb, Wgnlb, bgnl, Wglb, bgl, gb, MROWS, FF_, FF_);
    gemm_bf<3><<<dim3(D_/128, MROWS/128), blk>>>(gb, Wgob, bgo, x, y2, MROWS, D_, FF_, 0,0,0);
    ln_kernel<<<MROWS, D_>>>(y2, ln2g, ln2b, out, nullptr);
}

// round 7
// speedup vs baseline: 1.0981x; 1.0280x over previous
#include <cuda_runtime.h>
#include <cuda_bf16.h>
#include <cstdint>

#define B_   4
#define SM_  1024
#define SI_  4096
#define D_   256
#define H_   8
#define FF_  1024
#define MROWS (B_*SM_)
#define IROWS (B_*SI_)

typedef __nv_bfloat16  bf16;
typedef __nv_bfloat162 bf162;

// ---------------- scratch -------------------------------------------------
__device__ bf16  g_ib  [IROWS*D_];
__device__ bf16  g_sb  [MROWS*D_];
__device__ bf16  g_Wkvb[D_*512];          // packed Wk|Wv
__device__ float g_bkv [512];             // packed bk|bv
__device__ bf16  g_Wqb [H_*D_*D_];
__device__ bf16  g_Wob [H_*D_*D_];
__device__ bf16  g_Winb[D_*FF_];
__device__ bf16  g_Wgnlb[FF_*FF_];
__device__ bf16  g_Wglb [FF_*FF_];
__device__ bf16  g_Wgob [FF_*D_];
__device__ bf16  g_kvb [IROWS*512];       // ik|iv packed rows
__device__ bf16  g_mkvb[MROWS*512];       // mk|mv packed rows
__device__ bf16  g_qb  [H_*MROWS*D_];
__device__ bf16  g_ccb [MROWS*H_*D_];
__device__ float g_y   [MROWS*D_];
__device__ float g_x   [MROWS*D_];
__device__ bf16  g_xb  [MROWS*D_];
__device__ bf16  g_hb  [MROWS*FF_];
__device__ bf16  g_gb  [MROWS*FF_];
__device__ float g_y2  [MROWS*D_];

// ---------------- helpers --------------------------------------------------
__device__ __forceinline__ uint32_t sptr(const void* p){
    return (uint32_t)__cvta_generic_to_shared(p);
}
__device__ __forceinline__ float fexp2(float x){
    float y; asm("ex2.approx.f32 %0, %1;" : "=f"(y) : "f"(x)); return y;
}
__device__ __forceinline__ void ldsm4(uint32_t a[4], uint32_t addr){
    asm volatile("ldmatrix.sync.aligned.m8n8.x4.shared.b16 {%0,%1,%2,%3},[%4];"
        : "=r"(a[0]),"=r"(a[1]),"=r"(a[2]),"=r"(a[3]) : "r"(addr));
}
__device__ __forceinline__ void ldsm4t(uint32_t a[4], uint32_t addr){
    asm volatile("ldmatrix.sync.aligned.m8n8.x4.trans.shared.b16 {%0,%1,%2,%3},[%4];"
        : "=r"(a[0]),"=r"(a[1]),"=r"(a[2]),"=r"(a[3]) : "r"(addr));
}
__device__ __forceinline__ void mma16816(float c[4], const uint32_t a[4], const uint32_t b[2]){
    asm volatile("mma.sync.aligned.m16n8k16.row.col.f32.bf16.bf16.f32 "
        "{%0,%1,%2,%3},{%4,%5,%6,%7},{%8,%9},{%0,%1,%2,%3};"
        : "+f"(c[0]),"+f"(c[1]),"+f"(c[2]),"+f"(c[3])
        : "r"(a[0]),"r"(a[1]),"r"(a[2]),"r"(a[3]),"r"(b[0]),"r"(b[1]));
}
__device__ __forceinline__ void cp16(uint32_t dst, const void* src){
    asm volatile("cp.async.cg.shared.global [%0],[%1],16;" :: "r"(dst),"l"(src));
}
__device__ __forceinline__ void cpcommit(){ asm volatile("cp.async.commit_group;"); }
__device__ __forceinline__ void cpwait0(){ asm volatile("cp.async.wait_group 0;"); }
__device__ __forceinline__ void cpwait1(){ asm volatile("cp.async.wait_group 1;"); }
__device__ __forceinline__ void cpwait3(){ asm volatile("cp.async.wait_group 3;"); }

// ---------------- cvt kernels ------------------------------------------------
__global__ void cvt_io(const float* __restrict__ input, const float* __restrict__ state){
    int q = blockIdx.x*blockDim.x + threadIdx.x;
    const int NQI = IROWS*D_/4;
    const int NQS = MROWS*D_/4;
    if (q < NQI){
        float4 v = *(const float4*)(input + q*4);
        *(bf162*)(g_ib + q*4)   = __floats2bfloat162_rn(v.x,v.y);
        *(bf162*)(g_ib + q*4+2) = __floats2bfloat162_rn(v.z,v.w);
    } else if (q < NQI + NQS){
        int r = q - NQI;
        float4 v = *(const float4*)(state + r*4);
        *(bf162*)(g_sb + r*4)   = __floats2bfloat162_rn(v.x,v.y);
        *(bf162*)(g_sb + r*4+2) = __floats2bfloat162_rn(v.z,v.w);
    }
}

__device__ __forceinline__ void cvt4(const float* s, bf16* d){
    float4 v = *(const float4*)s;
    *(bf162*)(d)   = __floats2bfloat162_rn(v.x,v.y);
    *(bf162*)(d+2) = __floats2bfloat162_rn(v.z,v.w);
}

__global__ void cvt_w(const float* __restrict__ Wq, const float* __restrict__ Wo,
                      const float* __restrict__ Win, const float* __restrict__ Wgnl,
                      const float* __restrict__ Wgl, const float* __restrict__ Wgo,
                      const float* __restrict__ Wk, const float* __restrict__ Wv,
                      const float* __restrict__ bk, const float* __restrict__ bv)
{
    int q = blockIdx.x*blockDim.x + threadIdx.x;
    // segment sizes in quads
    const int S0=131072, S1=131072, S2=65536, S3=262144, S4=262144, S5=65536, S6=16384, S7=16384, S8=128;
    if (q < S0){ cvt4(Wq + q*4, g_Wqb + q*4); return; } q -= S0;
    if (q < S1){ cvt4(Wo + q*4, g_Wob + q*4); return; } q -= S1;
    if (q < S2){ cvt4(Win + q*4, g_Winb + q*4); return; } q -= S2;
    if (q < S3){ cvt4(Wgnl + q*4, g_Wgnlb + q*4); return; } q -= S3;
    if (q < S4){ cvt4(Wgl + q*4, g_Wglb + q*4); return; } q -= S4;
    if (q < S5){ cvt4(Wgo + q*4, g_Wgob + q*4); return; } q -= S5;
    if (q < S6){ int e=q*4, k=e>>8, j=e&255; cvt4(Wk + e, g_Wkvb + k*512 + j); return; } q -= S6;
    if (q < S7){ int e=q*4, k=e>>8, j=e&255; cvt4(Wv + e, g_Wkvb + k*512 + 256 + j); return; } q -= S7;
    if (q < S8){
        int j = q*4;
        const float* src = (j < 256) ? (bk + j) : (bv + j - 256);
        *(float4*)(g_bkv + j) = *(const float4*)src;
    }
}

// ---------------- bf16 GEMM (HMMA): C = A[M,K] @ B[K,N] + bias -------------
// OUTMODE: 0 bf16, 1 bf16+relu, 2 f32, 3 f32+residual R
template<int OUTMODE>
__global__ void __launch_bounds__(256) gemm_bf(
    const bf16* __restrict__ A, const bf16* __restrict__ Bw,
    const float* __restrict__ bias, const float* __restrict__ R,
    void* __restrict__ Cout, int M, int N, int K,
    long sB, long sBias, long sC)
{
    __shared__ __align__(16) bf16 smA[2][128*32];
    __shared__ __align__(16) bf16 smB[2][32*128];

    const int z = blockIdx.z;
    Bw   += (size_t)z*sB;
    bias += (size_t)z*sBias;

    const int m0 = blockIdx.y*128, n0 = blockIdx.x*128;
    const int t = threadIdx.x;
    const int w = t>>5, lane = t&31;
    const int wm = w>>1, wn = w&1;

    auto loadA = [&](int st, int k0){
        #pragma unroll
        for (int i=0;i<2;++i){
            int idx = t + i*256;
            int r = idx>>2, c = idx&3;
            int csw = c ^ ((r>>1)&3);
            cp16(sptr(&smA[st][(r*4+csw)*8]), A + (size_t)(m0+r)*K + k0 + c*8);
        }
    };
    auto loadB = [&](int st, int k0){
        #pragma unroll
        for (int i=0;i<2;++i){
            int idx = t + i*256;
            int r = idx>>4, c = idx&15;
            int csw = c ^ (r&7);
            cp16(sptr(&smB[st][(r*16+csw)*8]), Bw + (size_t)(k0+r)*N + n0 + c*8);
        }
    };

    float acc[2][8][4] = {};

    loadA(0,0); loadB(0,0); cpcommit();
    const int KT = K>>5;
    for (int kt=0; kt<KT; ++kt){
        int st = kt&1;
        if (kt+1<KT){ loadA(st^1,(kt+1)*32); loadB(st^1,(kt+1)*32); cpcommit(); cpwait1(); }
        else cpwait0();
        __syncthreads();

        #pragma unroll
        for (int ks=0; ks<2; ++ks){
            uint32_t af[2][4];
            #pragma unroll
            for (int mt=0; mt<2; ++mt){
                int r = wm*32 + mt*16 + (lane&7) + ((lane>>3)&1)*8;
                int c = ks*2 + (lane>>4);
                int csw = c ^ ((r>>1)&3);
                ldsm4(af[mt], sptr(&smA[st][(r*4+csw)*8]));
            }
            #pragma unroll
            for (int np=0; np<4; ++np){
                uint32_t bfr[4];
                int kr = ks*16 + (lane&7) + ((lane>>3)&1)*8;
                int c  = (wn*64 + np*16)/8 + (lane>>4);
                int csw = c ^ (kr&7);
                ldsm4t(bfr, sptr(&smB[st][(kr*16+csw)*8]));
                mma16816(acc[0][np*2+0], af[0], &bfr[0]);
                mma16816(acc[0][np*2+1], af[0], &bfr[2]);
                mma16816(acc[1][np*2+0], af[1], &bfr[0]);
                mma16816(acc[1][np*2+1], af[1], &bfr[2]);
            }
        }
        __syncthreads();
    }

    const int rbase = m0 + wm*32 + (lane>>2);
    const int cbase = n0 + wn*64 + (lane&3)*2;
    #pragma unroll
    for (int mt=0; mt<2; ++mt){
        #pragma unroll
        for (int nt=0; nt<8; ++nt){
            int row = rbase + mt*16;
            int col = cbase + nt*8;
            float b0 = bias[col], b1 = bias[col+1];
            float v0 = acc[mt][nt][0]+b0, v1 = acc[mt][nt][1]+b1;
            float v2 = acc[mt][nt][2]+b0, v3 = acc[mt][nt][3]+b1;
            if (OUTMODE==1){
                v0=fmaxf(v0,0.f); v1=fmaxf(v1,0.f); v2=fmaxf(v2,0.f); v3=fmaxf(v3,0.f);
            }
            if (OUTMODE==3){
                float2 r0 = *(const float2*)(R + (size_t)row*N + col);
                float2 r1 = *(const float2*)(R + (size_t)(row+8)*N + col);
                v0+=r0.x; v1+=r0.y; v2+=r1.x; v3+=r1.y;
            }
            if (OUTMODE<=1){
                bf16* C = (bf16*)Cout + (size_t)z*sC;
                *(bf162*)(C + (size_t)row*N + col)     = __floats2bfloat162_rn(v0,v1);
                *(bf162*)(C + (size_t)(row+8)*N + col) = __floats2bfloat162_rn(v2,v3);
            } else {
                float* C = (float*)Cout + (size_t)z*sC;
                *(float2*)(C + (size_t)row*N + col)     = make_float2(v0,v1);
                *(float2*)(C + (size_t)(row+8)*N + col) = make_float2(v2,v3);
            }
        }
    }
}

// ---------------- fused FFN gate: C = relu(A@B1+b1) * (A@B2+b2) ------------
__global__ void __launch_bounds__(256) dualgate(
    const bf16* __restrict__ A,
    const bf16* __restrict__ B1, const float* __restrict__ b1,
    const bf16* __restrict__ B2, const float* __restrict__ b2,
    bf16* __restrict__ C, int M, int N, int K)
{
    __shared__ __align__(16) bf16 smA [2][128*32];
    __shared__ __align__(16) bf16 smB1[2][32*64];
    __shared__ __align__(16) bf16 smB2[2][32*64];

    const int m0 = blockIdx.y*128, n0 = blockIdx.x*64;
    const int t = threadIdx.x;
    const int w = t>>5, lane = t&31;
    const int wm = w>>1, wn = w&1;

    auto loadA = [&](int st, int k0){
        #pragma unroll
        for (int i=0;i<2;++i){
            int idx = t + i*256;
            int r = idx>>2, c = idx&3;
            int csw = c ^ ((r>>1)&3);
            cp16(sptr(&smA[st][(r*4+csw)*8]), A + (size_t)(m0+r)*K + k0 + c*8);
        }
    };
    auto loadB = [&](int st, int k0){
        int r = t>>3, c = t&7;
        int csw = c ^ (r&7);
        cp16(sptr(&smB1[st][(r*8+csw)*8]), B1 + (size_t)(k0+r)*N + n0 + c*8);
        cp16(sptr(&smB2[st][(r*8+csw)*8]), B2 + (size_t)(k0+r)*N + n0 + c*8);
    };

    float acc1[2][4][4] = {};
    float acc2[2][4][4] = {};

    loadA(0,0); loadB(0,0); cpcommit();
    const int KT = K>>5;
    for (int kt=0; kt<KT; ++kt){
        int st = kt&1;
        if (kt+1<KT){ loadA(st^1,(kt+1)*32); loadB(st^1,(kt+1)*32); cpcommit(); cpwait1(); }
        else cpwait0();
        __syncthreads();

        #pragma unroll
        for (int ks=0; ks<2; ++ks){
            uint32_t af[2][4];
            #pragma unroll
            for (int mt=0; mt<2; ++mt){
                int r = wm*32 + mt*16 + (lane&7) + ((lane>>3)&1)*8;
                int c = ks*2 + (lane>>4);
                int csw = c ^ ((r>>1)&3);
                ldsm4(af[mt], sptr(&smA[st][(r*4+csw)*8]));
            }
            #pragma unroll
            for (int np=0; np<2; ++np){
                int kr = ks*16 + (lane&7) + ((lane>>3)&1)*8;
                int c  = (wn*32 + np*16)/8 + (lane>>4);
                int csw = c ^ (kr&7);
                uint32_t f1[4], f2[4];
                ldsm4t(f1, sptr(&smB1[st][(kr*8+csw)*8]));
                ldsm4t(f2, sptr(&smB2[st][(kr*8+csw)*8]));
                mma16816(acc1[0][np*2+0], af[0], &f1[0]);
                mma16816(acc1[0][np*2+1], af[0], &f1[2]);
                mma16816(acc1[1][np*2+0], af[1], &f1[0]);
                mma16816(acc1[1][np*2+1], af[1], &f1[2]);
                mma16816(acc2[0][np*2+0], af[0], &f2[0]);
                mma16816(acc2[0][np*2+1], af[0], &f2[2]);
                mma16816(acc2[1][np*2+0], af[1], &f2[0]);
                mma16816(acc2[1][np*2+1], af[1], &f2[2]);
            }
        }
        __syncthreads();
    }

    const int rbase = m0 + wm*32 + (lane>>2);
    const int cbase = n0 + wn*32 + (lane&3)*2;
    #pragma unroll
    for (int mt=0; mt<2; ++mt){
        #pragma unroll
        for (int nt=0; nt<4; ++nt){
            int row = rbase + mt*16;
            int col = cbase + nt*8;
            float c10 = b1[col], c11 = b1[col+1];
            float c20 = b2[col], c21 = b2[col+1];
            float v0 = fmaxf(acc1[mt][nt][0]+c10, 0.f)*(acc2[mt][nt][0]+c20);
            float v1 = fmaxf(acc1[mt][nt][1]+c11, 0.f)*(acc2[mt][nt][1]+c21);
            float v2 = fmaxf(acc1[mt][nt][2]+c10, 0.f)*(acc2[mt][nt][2]+c20);
            float v3 = fmaxf(acc1[mt][nt][3]+c11, 0.f)*(acc2[mt][nt][3]+c21);
            *(bf162*)(C + (size_t)row*N + col)     = __floats2bfloat162_rn(v0,v1);
            *(bf162*)(C + (size_t)(row+8)*N + col) = __floats2bfloat162_rn(v2,v3);
        }
    }
}

// ---------------- flash attention v3: 128 queries, 512 threads --------------
// smem: Q 64KB | K 2x32KB | V 2x32KB | P 128x72 bf16 | stats
#define FQ_OFF     0
#define FK_OFF(s)  (65536 + (s)*32768)
#define FV_OFF(s)  (131072 + (s)*32768)
#define FP_OFF     196608
#define FST_OFF    215040
#define FLASH_SMEM 217600
#define NT_        (SI_/64)
#define EXSC       0.09016844f   /* log2(e)/16 */

__global__ void __launch_bounds__(512,1) flash_bf3()
{
    extern __shared__ __align__(16) char sm[];
    bf16*  Qs     = (bf16*)(sm + FQ_OFF);
    bf16*  Ps     = (bf16*)(sm + FP_OFF);
    float* es_s   = (float*)(sm + FST_OFF);          // [128]
    float* rsum_s = (float*)(sm + FST_OFF + 512);    // [128]
    float* psum_s = (float*)(sm + FST_OFF + 1024);   // [128][2]

    const int t = threadIdx.x, w = t>>5, lane = t&31;
    const int h = blockIdx.y, b = blockIdx.z;
    const int m0 = blockIdx.x*128;

    auto qkvoff = [](int r, int c){ return (r*32 + (c ^ (r&7)))*8; };

    // Q + K0 (group1), V0 (g2), K1 (g3), V1 (g4)
    const bf16* qg = g_qb + ((size_t)h*MROWS + (size_t)b*SM_ + m0)*D_;
    #pragma unroll
    for (int i=0;i<8;++i){
        int idx = t + i*512;
        int r = idx>>5, c = idx&31;
        cp16(sptr(Qs + qkvoff(r,c)), qg + (size_t)r*D_ + c*8);
    }
    auto loadK = [&](int tile, int slot){
        const bf16* kg = g_kvb + ((size_t)b*SI_ + tile*64)*512;
        bf16* Ks = (bf16*)(sm + FK_OFF(slot));
        #pragma unroll
        for (int i=0;i<4;++i){
            int idx = t + i*512;
            int r = idx>>5, c = idx&31;
            cp16(sptr(Ks + qkvoff(r,c)), kg + (size_t)r*512 + c*8);
        }
    };
    auto loadV = [&](int tile, int slot){
        const bf16* vg = g_kvb + ((size_t)b*SI_ + tile*64)*512 + 256;
        bf16* Vs = (bf16*)(sm + FV_OFF(slot));
        #pragma unroll
        for (int i=0;i<4;++i){
            int idx = t + i*512;
            int r = idx>>5, c = idx&31;
            cp16(sptr(Vs + qkvoff(r,c)), vg + (size_t)r*512 + c*8);
        }
    };
    loadK(0,0); cpcommit();
    loadV(0,0); cpcommit();
    loadK(1,1); cpcommit();
    loadV(1,1); cpcommit();

    // self-score (global reads, overlap cp.async): es = exp(q . mk / 16)
    {
        int row = t>>2, quad = t&3;
        const bf162* q2 = (const bf162*)(qg + (size_t)row*D_ + quad*64);
        const bf162* k2 = (const bf162*)(g_mkvb + ((size_t)(b*SM_ + m0 + row))*512 + quad*64);
        float s = 0.f;
        #pragma unroll
        for (int j=0;j<32;++j){
            float2 qv = __bfloat1622float2(q2[j]);
            float2 kv = __bfloat1622float2(k2[j]);
            s += qv.x*kv.x + qv.y*kv.y;
        }
        s += __shfl_xor_sync(~0u, s, 1);
        s += __shfl_xor_sync(~0u, s, 2);
        if (quad==0) es_s[row] = fexp2(s*EXSC);
    }
    __syncthreads();   // es visible

    // O init = es * mv (bf16 from packed buffer)
    const int mh = w>>2, nq = w&3;
    float o[2][8][4];
    {
        const bf16* mvb = g_mkvb + ((size_t)(b*SM_ + m0))*512 + 256;
        #pragma unroll
        for (int mt=0;mt<2;++mt){
            int r0 = mh*32 + mt*16 + (lane>>2);
            float e0 = es_s[r0], e1 = es_s[r0+8];
            #pragma unroll
            for (int nt=0;nt<8;++nt){
                int col = nq*64 + nt*8 + (lane&3)*2;
                float2 f0 = __bfloat1622float2(*(const bf162*)(mvb + (size_t)r0*512 + col));
                float2 f1 = __bfloat1622float2(*(const bf162*)(mvb + (size_t)(r0+8)*512 + col));
                o[mt][nt][0]=e0*f0.x; o[mt][nt][1]=e0*f0.y;
                o[mt][nt][2]=e1*f1.x; o[mt][nt][3]=e1*f1.y;
            }
        }
    }

    const int sw_m = w>>1, sw_n = w&1;
    float ps0 = 0.f, ps1 = 0.f;

    for (int i=0; i<NT_; ++i){
        bf16* Ks = (bf16*)(sm + FK_OFF(i&1));
        bf16* Vs = (bf16*)(sm + FV_OFF(i&1));

        cpwait3(); __syncthreads();      // K(i) resident + visible

        // S = Q @ K^T (warp: 16 rows x 32 keys)
        float sa[4][4] = {};
        #pragma unroll
        for (int ks=0; ks<16; ++ks){
            uint32_t af[4];
            {
                int r = sw_m*16 + (lane&7) + ((lane>>3)&1)*8;
                int c = ks*2 + (lane>>4);
                ldsm4(af, sptr(Qs + qkvoff(r,c)));
            }
            #pragma unroll
            for (int np=0; np<2; ++np){
                uint32_t bfr[4];
                int r = sw_n*32 + np*16 + (lane&7) + ((lane>>4)&1)*8;
                int c = ks*2 + ((lane>>3)&1);
                ldsm4(bfr, sptr(Ks + qkvoff(r,c)));
                mma16816(sa[np*2+0], af, &bfr[0]);
                mma16816(sa[np*2+1], af, &bfr[2]);
            }
        }

        // exp (no max, fused scale) + P store + row-sum partials
        {
            int r0 = sw_m*16 + (lane>>2);
            #pragma unroll
            for (int i4=0;i4<4;++i4){
                float p0 = fexp2(sa[i4][0]*EXSC);
                float p1 = fexp2(sa[i4][1]*EXSC);
                float p2 = fexp2(sa[i4][2]*EXSC);
                float p3 = fexp2(sa[i4][3]*EXSC);
                ps0 += p0 + p1;
                ps1 += p2 + p3;
                int col = sw_n*32 + i4*8 + (lane&3)*2;
                *(bf162*)(Ps + r0*72 + col)     = __floats2bfloat162_rn(p0,p1);
                *(bf162*)(Ps + (r0+8)*72 + col) = __floats2bfloat162_rn(p2,p3);
            }
        }
        __syncthreads();   // P visible; K slot free

        if (i+2 < NT_) loadK(i+2, i&1);
        cpcommit();

        cpwait3(); __syncthreads();      // V(i) resident + visible

        // O += P @ V (warp: 32 rows x 64 d-cols)
        #pragma unroll
        for (int ks=0; ks<4; ++ks){
            uint32_t af[2][4];
            #pragma unroll
            for (int mt=0;mt<2;++mt){
                int r = mh*32 + mt*16 + (lane&7) + ((lane>>3)&1)*8;
                int c = ks*2 + (lane>>4);
                ldsm4(af[mt], sptr(Ps + r*72 + c*8));
            }
            #pragma unroll
            for (int np=0;np<4;++np){
                uint32_t bfr[4];
                int kr = ks*16 + (lane&7) + ((lane>>3)&1)*8;
                int c  = (nq*64 + np*16)/8 + (lane>>4);
                ldsm4t(bfr, sptr(Vs + qkvoff(kr,c)));
                mma16816(o[0][np*2+0], af[0], &bfr[0]);
                mma16816(o[0][np*2+1], af[0], &bfr[2]);
                mma16816(o[1][np*2+0], af[1], &bfr[0]);
                mma16816(o[1][np*2+1], af[1], &bfr[2]);
            }
        }
        __syncthreads();   // V slot free; P free

        if (i+2 < NT_) loadV(i+2, i&1);
        cpcommit();
    }

    // row-sum reduce + combine with self term
    ps0 += __shfl_xor_sync(~0u, ps0, 1);
    ps0 += __shfl_xor_sync(~0u, ps0, 2);
    ps1 += __shfl_xor_sync(~0u, ps1, 1);
    ps1 += __shfl_xor_sync(~0u, ps1, 2);
    if ((lane&3)==0){
        int r0 = sw_m*16 + (lane>>2);
        psum_s[r0*2 + sw_n]     = ps0;
        psum_s[(r0+8)*2 + sw_n] = ps1;
    }
    __syncthreads();
    if (t < 128) rsum_s[t] = es_s[t] + psum_s[t*2] + psum_s[t*2+1];
    __syncthreads();

    // normalize + write concat (bf16)
    #pragma unroll
    for (int mt=0;mt<2;++mt){
        int r0 = mh*32 + mt*16 + (lane>>2);
        float i0 = 1.f/rsum_s[r0], i1 = 1.f/rsum_s[r0+8];
        bf16* c0 = g_ccb + ((size_t)(b*SM_ + m0 + r0)*(H_*D_)) + h*D_;
        bf16* c1 = g_ccb + ((size_t)(b*SM_ + m0 + r0 + 8)*(H_*D_)) + h*D_;
        #pragma unroll
        for (int nt=0;nt<8;++nt){
            int col = nq*64 + nt*8 + (lane&3)*2;
            *(bf162*)(c0+col) = __floats2bfloat162_rn(o[mt][nt][0]*i0, o[mt][nt][1]*i0);
            *(bf162*)(c1+col) = __floats2bfloat162_rn(o[mt][nt][2]*i1, o[mt][nt][3]*i1);
        }
    }
}

// ---------------- LayerNorm ------------------------------------------------
__global__ void ln_kernel(const float* __restrict__ Y, const float* __restrict__ g,
                          const float* __restrict__ bb, float* __restrict__ X,
                          bf16* __restrict__ Xb)
{
    const int row = blockIdx.x;
    const int t = threadIdx.x;
    const float v = Y[(size_t)row*D_ + t];
    __shared__ float red[8];
    __shared__ float stat;

    float s = v;
    #pragma unroll
    for (int o = 16; o; o >>= 1) s += __shfl_xor_sync(0xffffffffu, s, o);
    if ((t & 31) == 0) red[t >> 5] = s;
    __syncthreads();
    if (t == 0) {
        float tot = 0.f;
        #pragma unroll
        for (int i = 0; i < 8; ++i) tot += red[i];
        stat = tot * (1.f / D_);
    }
    __syncthreads();
    const float mean = stat;
    const float d = v - mean;

    s = d * d;
    #pragma unroll
    for (int o = 16; o; o >>= 1) s += __shfl_xor_sync(0xffffffffu, s, o);
    __syncthreads();
    if ((t & 31) == 0) red[t >> 5] = s;
    __syncthreads();
    if (t == 0) {
        float tot = 0.f;
        #pragma unroll
        for (int i = 0; i < 8; ++i) tot += red[i];
        stat = tot * (1.f / D_);
    }
    __syncthreads();
    float out = d * rsqrtf(stat + 1e-6f) * g[t] + bb[t];
    X[(size_t)row*D_ + t] = out;
    if (Xb) Xb[(size_t)row*D_ + t] = __float2bfloat16(out);
}

// ---------------- launch ----------------------------------------------------
extern "C" void kernel_launch(void* const* d_in, const int* in_sizes, int n_in,
                              void* d_out, int out_size)
{
    (void)in_sizes; (void)n_in; (void)out_size;
    const float* state = (const float*)d_in[0];
    const float* input = (const float*)d_in[1];
    const float* Wk    = (const float*)d_in[2];
    const float* bk    = (const float*)d_in[3];
    const float* Wv    = (const float*)d_in[4];
    const float* bv    = (const float*)d_in[5];
    const float* Wq    = (const float*)d_in[6];
    const float* bq    = (const float*)d_in[7];
    const float* Wo    = (const float*)d_in[8];
    const float* bo    = (const float*)d_in[9];
    const float* ln1g  = (const float*)d_in[10];
    const float* ln1b  = (const float*)d_in[11];
    const float* Win   = (const float*)d_in[12];
    const float* bin   = (const float*)d_in[13];
    const float* Wgnl  = (const float*)d_in[14];
    const float* bgnl  = (const float*)d_in[15];
    const float* Wgl   = (const float*)d_in[16];
    const float* bgl   = (const float*)d_in[17];
    const float* Wgo   = (const float*)d_in[18];
    const float* bgo   = (const float*)d_in[19];
    const float* ln2g  = (const float*)d_in[20];
    const float* ln2b  = (const float*)d_in[21];
    float* out = (float*)d_out;

    bf16 *ib,*sb,*Wkvb,*Wqb,*Wob,*Winb,*Wgnlb,*Wglb,*Wgob;
    bf16 *kvb,*mkvb,*qb,*ccb,*xb,*hb,*gb;
    float *bkv,*y,*x,*y2;
    cudaGetSymbolAddress((void**)&ib,   g_ib);
    cudaGetSymbolAddress((void**)&sb,   g_sb);
    cudaGetSymbolAddress((void**)&Wkvb, g_Wkvb);
    cudaGetSymbolAddress((void**)&bkv,  g_bkv);
    cudaGetSymbolAddress((void**)&Wqb,  g_Wqb);
    cudaGetSymbolAddress((void**)&Wob,  g_Wob);
    cudaGetSymbolAddress((void**)&Winb, g_Winb);
    cudaGetSymbolAddress((void**)&Wgnlb,g_Wgnlb);
    cudaGetSymbolAddress((void**)&Wglb, g_Wglb);
    cudaGetSymbolAddress((void**)&Wgob, g_Wgob);
    cudaGetSymbolAddress((void**)&kvb,  g_kvb);
    cudaGetSymbolAddress((void**)&mkvb, g_mkvb);
    cudaGetSymbolAddress((void**)&qb,   g_qb);
    cudaGetSymbolAddress((void**)&ccb,  g_ccb);
    cudaGetSymbolAddress((void**)&y,    g_y);
    cudaGetSymbolAddress((void**)&x,    g_x);
    cudaGetSymbolAddress((void**)&xb,   g_xb);
    cudaGetSymbolAddress((void**)&hb,   g_hb);
    cudaGetSymbolAddress((void**)&gb,   g_gb);
    cudaGetSymbolAddress((void**)&y2,   g_y2);

    cudaFuncSetAttribute(flash_bf3, cudaFuncAttributeMaxDynamicSharedMemorySize, FLASH_SMEM);

    dim3 blk(256);
    // launch 0: io converts
    cvt_io<<<((IROWS+MROWS)*D_/4 + 255)/256, 256>>>(input, state);
    // launch 1: weight converts + Wk|Wv pack + bk|bv pack
    cvt_w<<<(950400 + 255)/256, 256>>>(Wq, Wo, Win, Wgnl, Wgl, Wgo, Wk, Wv, bk, bv);
    // launch 2: input K|V projection (N=512 packed)
    gemm_bf<0><<<dim3(4, IROWS/128), blk>>>(ib, Wkvb, bkv, nullptr, kvb, IROWS, 512, D_, 0,0,0);
    // launch 3: state K|V projection
    gemm_bf<0><<<dim3(4, MROWS/128), blk>>>(sb, Wkvb, bkv, nullptr, mkvb, MROWS, 512, D_, 0,0,0);
    // launch 4: per-head Q projection (batched)
    gemm_bf<0><<<dim3(2, MROWS/128, H_), blk>>>(sb, Wqb, bq, nullptr, qb,
                                                MROWS, D_, D_, (long)D_*D_, D_, (long)MROWS*D_);
    // launch 5: flash attention  (ncu -s 5 -c 1 captures this one)
    flash_bf3<<<dim3(SM_/128, H_, B_), 512, FLASH_SMEM>>>();
    // output proj + residual, LN1
    gemm_bf<3><<<dim3(2, MROWS/128), blk>>>(ccb, Wob, bo, state, y, MROWS, D_, H_*D_, 0,0,0);
    ln_kernel<<<MROWS, D_>>>(y, ln1g, ln1b, x, xb);
    // FFN
    gemm_bf<1><<<dim3(FF_/128, MROWS/128), blk>>>(xb, Winb, bin, nullptr, hb, MROWS, FF_, D_, 0,0,0);
    dualgate<<<dim3(FF_/64, MROWS/128), blk>>>(hb, Wgnlb, bgnl, Wglb, bgl, gb, MROWS, FF_, FF_);
    gemm_bf<3><<<dim3(2, MROWS/128), blk>>>(gb, Wgob, bgo, x, y2, MROWS, D_, FF_, 0,0,0);
    ln_kernel<<<MROWS, D_>>>(y2, ln2g, ln2b, out, nullptr);
}